// round 3
// baseline (speedup 1.0000x reference)
#include <cuda_runtime.h>
#include <math_constants.h>

// Problem constants
#define PB 4
#define PT 2048
#define PC 1024
#define PH 16
#define PDK 64
#define NTOK (PB * PT)      // 8192
#define M3 (3 * PC)         // 3072

typedef unsigned long long ull;

// ---- f32x2 packed helpers (sm_103a; ptxas never emits FFMA2 from C++) ----
__device__ __forceinline__ void ffma2(ull& d, ull a, ull b) {
    asm("fma.rn.f32x2 %0, %1, %2, %0;" : "+l"(d) : "l"(a), "l"(b));
}
__device__ __forceinline__ void fmul2(ull& d, ull a) {
    asm("mul.rn.f32x2 %0, %0, %1;" : "+l"(d) : "l"(a));
}
__device__ __forceinline__ ull dup2(float a) {
    ull r;
    asm("mov.b64 %0, {%1, %1};" : "=l"(r) : "r"(__float_as_uint(a)));
    return r;
}
__device__ __forceinline__ float2 unpack2(ull v) {
    float2 f;
    asm("mov.b64 {%0, %1}, %2;" : "=f"(f.x), "=f"(f.y) : "l"(v));
    return f;
}

// Scratch: q,k,v in [B,H,T,dk] layout; y in [B,T,C] layout
__device__ float g_q[NTOK * PC];
__device__ float g_k[NTOK * PC];
__device__ float g_v[NTOK * PC];
__device__ float g_y[NTOK * PC];

// ---------------------------------------------------------------------------
// QKV GEMM: qkv[n,m] = sum_k x[n,k] * w[m,k] + bias[m], scatter to q/k/v.
// Block tile 64(n) x 128(m), BK=16, 256 threads, micro 4(n) x 8(m),
// accumulators packed along m as f32x2.
// ---------------------------------------------------------------------------
__global__ __launch_bounds__(256) void qkv_gemm_kernel(
    const float* __restrict__ x, const float* __restrict__ w,
    const float* __restrict__ bias)
{
    __shared__ __align__(16) float As[16][68];    // [k][n]
    __shared__ __align__(16) float Bs[16][132];   // [k][m]
    const int tid = threadIdx.x;
    const int tx = tid & 15, ty = tid >> 4;
    const int m0 = blockIdx.x * 128;
    const int n0 = blockIdx.y * 64;

    const int ar = tid >> 2;            // 0..63  (A row)
    const int ak = (tid & 3) << 2;      // 0,4,8,12 (A k-quad)

    ull acc[4][4];
    #pragma unroll
    for (int i = 0; i < 4; i++)
        #pragma unroll
        for (int j = 0; j < 4; j++) acc[i][j] = 0ull;

    for (int k0 = 0; k0 < PC; k0 += 16) {
        // Load A tile (64x16) -> As transposed
        {
            float4 a4 = *(const float4*)(x + (size_t)(n0 + ar) * PC + k0 + ak);
            As[ak + 0][ar] = a4.x;
            As[ak + 1][ar] = a4.y;
            As[ak + 2][ar] = a4.z;
            As[ak + 3][ar] = a4.w;
        }
        // Load B tile (128x16) -> Bs transposed
        #pragma unroll
        for (int h = 0; h < 2; h++) {
            const int f = tid + h * 256;
            const int br = f >> 2, bk = (f & 3) << 2;
            float4 b4 = *(const float4*)(w + (size_t)(m0 + br) * PC + k0 + bk);
            Bs[bk + 0][br] = b4.x;
            Bs[bk + 1][br] = b4.y;
            Bs[bk + 2][br] = b4.z;
            Bs[bk + 3][br] = b4.w;
        }
        __syncthreads();
        #pragma unroll
        for (int kk = 0; kk < 16; kk++) {
            float4 a4 = *(const float4*)&As[kk][ty << 2];
            ulonglong2 b01 = *(const ulonglong2*)&Bs[kk][tx << 3];
            ulonglong2 b23 = *(const ulonglong2*)&Bs[kk][(tx << 3) + 4];
            ull ad[4] = {dup2(a4.x), dup2(a4.y), dup2(a4.z), dup2(a4.w)};
            #pragma unroll
            for (int i = 0; i < 4; i++) {
                ffma2(acc[i][0], ad[i], b01.x);
                ffma2(acc[i][1], ad[i], b01.y);
                ffma2(acc[i][2], ad[i], b23.x);
                ffma2(acc[i][3], ad[i], b23.y);
            }
        }
        __syncthreads();
    }
    // Epilogue: scatter into q/k/v [B,H,T,dk]
    #pragma unroll
    for (int i = 0; i < 4; i++) {
        const int n = n0 + (ty << 2) + i;
        const int bidx = n / PT, tok = n % PT;
        #pragma unroll
        for (int jj = 0; jj < 4; jj++) {
            float2 v2 = unpack2(acc[i][jj]);
            #pragma unroll
            for (int e = 0; e < 2; e++) {
                const int m = m0 + (tx << 3) + (jj << 1) + e;
                const float val = (e ? v2.y : v2.x) + bias[m];
                const int sec = m >> 10;
                const int c = m & (PC - 1);
                const int hh = c >> 6, d = c & 63;
                float* dst = (sec == 0) ? g_q : (sec == 1) ? g_k : g_v;
                dst[(((size_t)bidx * PH + hh) * PT + tok) * PDK + d] = val;
            }
        }
    }
}

// ---------------------------------------------------------------------------
// Flash attention: one block per (q-tile, head, batch). Br=Bc=64, dk=64.
// 256 threads; thread (tx,ty) owns 4 rows x 4 cols, inner products via f32x2.
// ---------------------------------------------------------------------------
#define ATT_SMEM_FLOATS (64 * 68 * 2 + 64 * 64 * 2)

__global__ __launch_bounds__(256) void attn_kernel()
{
    extern __shared__ float sm[];
    float* Qt = sm;                 // [d][r], ld 68 (pre-scaled by 1/8)
    float* Kt = Qt + 64 * 68;       // [d][c], ld 68
    float* Vs = Kt + 64 * 68;       // [j][d], ld 64
    float* Pt = Vs + 64 * 64;       // [r][c], ld 64

    const int qt = blockIdx.x, hh = blockIdx.y, bidx = blockIdx.z;
    const float* qbase = g_q + (((size_t)bidx * PH + hh) * PT + qt * 64) * PDK;
    const float* kbase = g_k + (((size_t)bidx * PH + hh) * PT) * PDK;
    const float* vbase = g_v + (((size_t)bidx * PH + hh) * PT) * PDK;

    const int tid = threadIdx.x;
    const int tx = tid & 15, ty = tid >> 4;
    const int lj = tid >> 2;               // 0..63 (load row)
    const int ld0 = (tid & 3) << 4;        // 0,16,32,48 (load d-chunk)

    // Load Q tile, transposed, pre-scaled.
    #pragma unroll
    for (int i = 0; i < 4; i++) {
        float4 t4 = *(const float4*)(qbase + (size_t)lj * PDK + ld0 + i * 4);
        const int d = ld0 + i * 4;
        Qt[(d + 0) * 68 + lj] = t4.x * 0.125f;
        Qt[(d + 1) * 68 + lj] = t4.y * 0.125f;
        Qt[(d + 2) * 68 + lj] = t4.z * 0.125f;
        Qt[(d + 3) * 68 + lj] = t4.w * 0.125f;
    }

    float mrow[4], lrow[4];
    ull op[4][2];                        // O accumulator, packed along c
    #pragma unroll
    for (int i = 0; i < 4; i++) {
        mrow[i] = -CUDART_INF_F;
        lrow[i] = 0.0f;
        op[i][0] = 0ull;
        op[i][1] = 0ull;
    }

    for (int kt = 0; kt < PT / 64; kt++) {
        __syncthreads();   // previous PV done reading Vs/Pt
        #pragma unroll
        for (int i = 0; i < 4; i++) {
            float4 t4 = *(const float4*)(kbase + ((size_t)kt * 64 + lj) * PDK + ld0 + i * 4);
            const int d = ld0 + i * 4;
            Kt[(d + 0) * 68 + lj] = t4.x;
            Kt[(d + 1) * 68 + lj] = t4.y;
            Kt[(d + 2) * 68 + lj] = t4.z;
            Kt[(d + 3) * 68 + lj] = t4.w;
            float4 v4 = *(const float4*)(vbase + ((size_t)kt * 64 + lj) * PDK + ld0 + i * 4);
            *(float4*)&Vs[lj * 64 + ld0 + i * 4] = v4;
        }
        __syncthreads();

        // S = (Q*scale) K^T, packed along j (2 f32x2 per row)
        ull sp[4][2];
        #pragma unroll
        for (int i = 0; i < 4; i++) { sp[i][0] = 0ull; sp[i][1] = 0ull; }
        #pragma unroll
        for (int d = 0; d < 64; d++) {
            float4 a4 = *(const float4*)&Qt[d * 68 + (ty << 2)];
            ulonglong2 b2 = *(const ulonglong2*)&Kt[d * 68 + (tx << 2)];
            ull ad[4] = {dup2(a4.x), dup2(a4.y), dup2(a4.z), dup2(a4.w)};
            #pragma unroll
            for (int i = 0; i < 4; i++) {
                ffma2(sp[i][0], ad[i], b2.x);
                ffma2(sp[i][1], ad[i], b2.y);
            }
        }
        // Unpack S
        float s[4][4];
        #pragma unroll
        for (int i = 0; i < 4; i++) {
            float2 u0 = unpack2(sp[i][0]);
            float2 u1 = unpack2(sp[i][1]);
            s[i][0] = u0.x; s[i][1] = u0.y; s[i][2] = u1.x; s[i][3] = u1.y;
        }

        // Online softmax per row
        #pragma unroll
        for (int i = 0; i < 4; i++) {
            float mx = fmaxf(fmaxf(s[i][0], s[i][1]), fmaxf(s[i][2], s[i][3]));
            #pragma unroll
            for (int off = 8; off >= 1; off >>= 1)
                mx = fmaxf(mx, __shfl_xor_sync(0xffffffffu, mx, off));
            const float mnew = fmaxf(mrow[i], mx);
            const float alpha = __expf(mrow[i] - mnew);
            mrow[i] = mnew;
            float rs = 0.0f;
            #pragma unroll
            for (int j = 0; j < 4; j++) {
                const float p = __expf(s[i][j] - mnew);
                s[i][j] = p;
                rs += p;
            }
            #pragma unroll
            for (int off = 8; off >= 1; off >>= 1)
                rs += __shfl_xor_sync(0xffffffffu, rs, off);
            lrow[i] = lrow[i] * alpha + rs;
            ull al = dup2(alpha);
            fmul2(op[i][0], al);
            fmul2(op[i][1], al);
        }

        // Store P (natural layout), then O += P V
        #pragma unroll
        for (int i = 0; i < 4; i++) {
            float4 p4 = make_float4(s[i][0], s[i][1], s[i][2], s[i][3]);
            *(float4*)&Pt[((ty << 2) + i) * 64 + (tx << 2)] = p4;
        }
        __syncthreads();

        #pragma unroll
        for (int j = 0; j < 64; j++) {
            ulonglong2 v2 = *(const ulonglong2*)&Vs[j * 64 + (tx << 2)];
            float p0 = Pt[((ty << 2) + 0) * 64 + j];
            float p1 = Pt[((ty << 2) + 1) * 64 + j];
            float p2 = Pt[((ty << 2) + 2) * 64 + j];
            float p3 = Pt[((ty << 2) + 3) * 64 + j];
            ull pd[4] = {dup2(p0), dup2(p1), dup2(p2), dup2(p3)};
            #pragma unroll
            for (int i = 0; i < 4; i++) {
                ffma2(op[i][0], pd[i], v2.x);
                ffma2(op[i][1], pd[i], v2.y);
            }
        }
    }

    // Normalize and write y in [B,T,C] layout
    #pragma unroll
    for (int i = 0; i < 4; i++) {
        const float inv = 1.0f / lrow[i];
        const int tok = qt * 64 + (ty << 2) + i;
        float2 u0 = unpack2(op[i][0]);
        float2 u1 = unpack2(op[i][1]);
        float4 r4 = make_float4(u0.x * inv, u0.y * inv, u1.x * inv, u1.y * inv);
        *(float4*)&g_y[((size_t)bidx * PT + tok) * PC + hh * PDK + (tx << 2)] = r4;
    }
}

// ---------------------------------------------------------------------------
// Output projection: out[n,m] = sum_k y[n,k] * w_proj[m,k] + b_proj[m]
// Same shape as qkv_gemm; dense float4 epilogue.
// ---------------------------------------------------------------------------
__global__ __launch_bounds__(256) void proj_gemm_kernel(
    const float* __restrict__ w, const float* __restrict__ bias,
    float* __restrict__ out)
{
    __shared__ __align__(16) float As[16][68];
    __shared__ __align__(16) float Bs[16][132];
    const int tid = threadIdx.x;
    const int tx = tid & 15, ty = tid >> 4;
    const int m0 = blockIdx.x * 128;
    const int n0 = blockIdx.y * 64;

    const int ar = tid >> 2;
    const int ak = (tid & 3) << 2;

    ull acc[4][4];
    #pragma unroll
    for (int i = 0; i < 4; i++)
        #pragma unroll
        for (int j = 0; j < 4; j++) acc[i][j] = 0ull;

    for (int k0 = 0; k0 < PC; k0 += 16) {
        {
            float4 a4 = *(const float4*)(g_y + (size_t)(n0 + ar) * PC + k0 + ak);
            As[ak + 0][ar] = a4.x;
            As[ak + 1][ar] = a4.y;
            As[ak + 2][ar] = a4.z;
            As[ak + 3][ar] = a4.w;
        }
        #pragma unroll
        for (int h = 0; h < 2; h++) {
            const int f = tid + h * 256;
            const int br = f >> 2, bk = (f & 3) << 2;
            float4 b4 = *(const float4*)(w + (size_t)(m0 + br) * PC + k0 + bk);
            Bs[bk + 0][br] = b4.x;
            Bs[bk + 1][br] = b4.y;
            Bs[bk + 2][br] = b4.z;
            Bs[bk + 3][br] = b4.w;
        }
        __syncthreads();
        #pragma unroll
        for (int kk = 0; kk < 16; kk++) {
            float4 a4 = *(const float4*)&As[kk][ty << 2];
            ulonglong2 b01 = *(const ulonglong2*)&Bs[kk][tx << 3];
            ulonglong2 b23 = *(const ulonglong2*)&Bs[kk][(tx << 3) + 4];
            ull ad[4] = {dup2(a4.x), dup2(a4.y), dup2(a4.z), dup2(a4.w)};
            #pragma unroll
            for (int i = 0; i < 4; i++) {
                ffma2(acc[i][0], ad[i], b01.x);
                ffma2(acc[i][1], ad[i], b01.y);
                ffma2(acc[i][2], ad[i], b23.x);
                ffma2(acc[i][3], ad[i], b23.y);
            }
        }
        __syncthreads();
    }
    #pragma unroll
    for (int i = 0; i < 4; i++) {
        const int n = n0 + (ty << 2) + i;
        const int mb = m0 + (tx << 3);
        float2 u0 = unpack2(acc[i][0]);
        float2 u1 = unpack2(acc[i][1]);
        float2 u2 = unpack2(acc[i][2]);
        float2 u3 = unpack2(acc[i][3]);
        float4 r0 = make_float4(u0.x + bias[mb + 0], u0.y + bias[mb + 1],
                                u1.x + bias[mb + 2], u1.y + bias[mb + 3]);
        float4 r1 = make_float4(u2.x + bias[mb + 4], u2.y + bias[mb + 5],
                                u3.x + bias[mb + 6], u3.y + bias[mb + 7]);
        *(float4*)(out + (size_t)n * PC + mb) = r0;
        *(float4*)(out + (size_t)n * PC + mb + 4) = r1;
    }
}

// ---------------------------------------------------------------------------
extern "C" void kernel_launch(void* const* d_in, const int* in_sizes, int n_in,
                              void* d_out, int out_size)
{
    const float* x      = (const float*)d_in[0];
    const float* w_attn = (const float*)d_in[1];
    const float* b_attn = (const float*)d_in[2];
    const float* w_proj = (const float*)d_in[3];
    const float* b_proj = (const float*)d_in[4];
    float* out = (float*)d_out;

    static_assert(ATT_SMEM_FLOATS * 4 == 67584, "smem layout");
    cudaFuncSetAttribute(attn_kernel,
                         cudaFuncAttributeMaxDynamicSharedMemorySize,
                         ATT_SMEM_FLOATS * 4);

    dim3 g1(M3 / 128, NTOK / 64);   // 24 x 128
    qkv_gemm_kernel<<<g1, 256>>>(x, w_attn, b_attn);

    dim3 g2(PT / 64, PH, PB);       // 32 x 16 x 4
    attn_kernel<<<g2, 256, ATT_SMEM_FLOATS * 4>>>();

    dim3 g3(PC / 128, NTOK / 64);   // 8 x 128
    proj_gemm_kernel<<<g3, 256>>>(w_proj, b_proj, out);
}

// round 5
// speedup vs baseline: 1.5013x; 1.5013x over previous
#include <cuda_runtime.h>
#include <cuda_bf16.h>
#include <math_constants.h>
#include <cstdint>

// Problem constants
#define PB 4
#define PT 2048
#define PC 1024
#define PH 16
#define PDK 64
#define NTOK (PB * PT)      // 8192
#define M3 (3 * PC)         // 3072

// fp32 scratch
__device__ float g_q[NTOK * PC];
__device__ float g_k[NTOK * PC];
__device__ float g_v[NTOK * PC];
__device__ float g_y[NTOK * PC];
// bf16 split planes
__device__ __nv_bfloat16 g_xh[NTOK * PC], g_xl[NTOK * PC];
__device__ __nv_bfloat16 g_yh[NTOK * PC], g_yl[NTOK * PC];
__device__ __nv_bfloat16 g_wah[M3 * PC],  g_wal[M3 * PC];
__device__ __nv_bfloat16 g_wph[PC * PC],  g_wpl[PC * PC];

// ---------------------------------------------------------------------------
// Split-convert: fp32 -> (hi bf16, lo bf16), lo = x - (float)hi
// ---------------------------------------------------------------------------
__global__ __launch_bounds__(256) void conv_split_kernel(
    const float* __restrict__ src, __nv_bfloat16* __restrict__ hi,
    __nv_bfloat16* __restrict__ lo)
{
    const int i = (blockIdx.x * 256 + threadIdx.x) * 4;
    float4 v = *(const float4*)(src + i);
    __nv_bfloat162 h0 = __floats2bfloat162_rn(v.x, v.y);
    __nv_bfloat162 h1 = __floats2bfloat162_rn(v.z, v.w);
    __nv_bfloat162 l0 = __floats2bfloat162_rn(v.x - __bfloat162float(h0.x),
                                              v.y - __bfloat162float(h0.y));
    __nv_bfloat162 l1 = __floats2bfloat162_rn(v.z - __bfloat162float(h1.x),
                                              v.w - __bfloat162float(h1.y));
    *(uint2*)(hi + i) = make_uint2(*(const uint32_t*)&h0, *(const uint32_t*)&h1);
    *(uint2*)(lo + i) = make_uint2(*(const uint32_t*)&l0, *(const uint32_t*)&l1);
}

// ---------------------------------------------------------------------------
// Tensor-core GEMM via mma.sync (HMMA): D[m=token][n=feature]
//   D = X * W^T + bias, with X,W given as hi/lo bf16 planes (k-major, K=1024)
// Block 128x128, 8 warps (2m x 4n), warp tile 64x32, BK=32 halves, 2 stages.
// MODE 0: scatter q/k/v.  MODE 1: write out[n_tok][f].
// ---------------------------------------------------------------------------
__device__ __forceinline__ uint32_t smem_u32(const void* p) {
    uint32_t a;
    asm("{ .reg .u64 t; cvta.to.shared.u64 t, %1; cvt.u32.u64 %0, t; }"
        : "=r"(a) : "l"(p));
    return a;
}
__device__ __forceinline__ void ldsm_x4(uint32_t addr, uint32_t& r0, uint32_t& r1,
                                        uint32_t& r2, uint32_t& r3) {
    asm volatile("ldmatrix.sync.aligned.m8n8.x4.shared.b16 {%0,%1,%2,%3}, [%4];"
                 : "=r"(r0), "=r"(r1), "=r"(r2), "=r"(r3) : "r"(addr));
}
__device__ __forceinline__ void mma16816(float* c, const uint32_t* a,
                                         uint32_t b0, uint32_t b1) {
    asm volatile(
        "mma.sync.aligned.m16n8k16.row.col.f32.bf16.bf16.f32 "
        "{%0,%1,%2,%3}, {%4,%5,%6,%7}, {%8,%9}, {%0,%1,%2,%3};"
        : "+f"(c[0]), "+f"(c[1]), "+f"(c[2]), "+f"(c[3])
        : "r"(a[0]), "r"(a[1]), "r"(a[2]), "r"(a[3]), "r"(b0), "r"(b1));
}

#define ROWB 80                     // smem row stride bytes (64B data + 16B pad)
#define PARTB (128 * ROWB)          // 10240 bytes per (matrix, part) tile
#define STAGEB (4 * PARTB)          // Ah, Al, Bh, Bl
#define GK_SMEM (2 * STAGEB)        // 81920

template <int MODE>
__global__ __launch_bounds__(256) void tc_gemm_kernel(
    const __nv_bfloat16* __restrict__ Ah_g, const __nv_bfloat16* __restrict__ Al_g,
    const __nv_bfloat16* __restrict__ Bh_g, const __nv_bfloat16* __restrict__ Bl_g,
    const float* __restrict__ bias, float* __restrict__ outp)
{
    extern __shared__ __align__(16) char smem[];
    const uint32_t sbase = smem_u32(smem);
    const int tid = threadIdx.x;
    const int wid = tid >> 5, lid = tid & 31;
    const int wm = wid >> 2, wn = wid & 3;
    const int fb = blockIdx.x * 128;     // feature block (n)
    const int mb = blockIdx.y * 128;     // token block (m)

    // Global sources per part: A=X rows at mb, B=W rows at fb
    const __nv_bfloat16* srcs[4] = {
        Ah_g + (size_t)mb * PC, Al_g + (size_t)mb * PC,
        Bh_g + (size_t)fb * PC, Bl_g + (size_t)fb * PC };

    // This thread's 8 load slots: part p = t>>1, chunk c = ((t&1)<<8)|tid
    // chunk c: row = c>>2, 16B quad = c&3
    float c[4][4][4];
    #pragma unroll
    for (int i = 0; i < 4; i++)
        #pragma unroll
        for (int j = 0; j < 4; j++)
            #pragma unroll
            for (int e = 0; e < 4; e++) c[i][j][e] = 0.0f;

    // Prologue: load stage 0
    #pragma unroll
    for (int t = 0; t < 8; t++) {
        const int p = t >> 1;
        const int ch = ((t & 1) << 8) | tid;
        const int row = ch >> 2, kq = (ch & 3) << 3;
        uint4 v = *(const uint4*)(srcs[p] + (size_t)row * PC + kq);
        *(uint4*)(smem + p * PARTB + row * ROWB + ((ch & 3) << 4)) = v;
    }
    __syncthreads();

    const int lr = lid & 15;
    const int lk2 = ((lid >> 4) << 3) * 2;   // byte offset of k-half select

    for (int ks = 0; ks < 32; ks++) {
        const int cur = ks & 1;
        uint4 stv[8];
        if (ks + 1 < 32) {
            const int kh = (ks + 1) * 32;
            #pragma unroll
            for (int t = 0; t < 8; t++) {
                const int p = t >> 1;
                const int ch = ((t & 1) << 8) | tid;
                const int row = ch >> 2, kq = (ch & 3) << 3;
                stv[t] = *(const uint4*)(srcs[p] + (size_t)row * PC + kh + kq);
            }
        }
        const uint32_t stb = sbase + cur * STAGEB;
        #pragma unroll
        for (int k16 = 0; k16 < 2; k16++) {
            const uint32_t kb = k16 * 32 + lk2;
            uint32_t ah[4][4], al[4][4];
            #pragma unroll
            for (int mt = 0; mt < 4; mt++) {
                const uint32_t ra = (wm * 64 + mt * 16 + lr) * ROWB + kb;
                ldsm_x4(stb + 0 * PARTB + ra, ah[mt][0], ah[mt][1], ah[mt][2], ah[mt][3]);
                ldsm_x4(stb + 1 * PARTB + ra, al[mt][0], al[mt][1], al[mt][2], al[mt][3]);
            }
            uint32_t bh[4][2], bl[4][2];
            #pragma unroll
            for (int np = 0; np < 2; np++) {
                const uint32_t rb = (wn * 32 + np * 16 + lr) * ROWB + kb;
                uint32_t r0, r1, r2, r3;
                ldsm_x4(stb + 2 * PARTB + rb, r0, r1, r2, r3);
                bh[np * 2][0] = r0; bh[np * 2][1] = r2;
                bh[np * 2 + 1][0] = r1; bh[np * 2 + 1][1] = r3;
                ldsm_x4(stb + 3 * PARTB + rb, r0, r1, r2, r3);
                bl[np * 2][0] = r0; bl[np * 2][1] = r2;
                bl[np * 2 + 1][0] = r1; bl[np * 2 + 1][1] = r3;
            }
            #pragma unroll
            for (int mt = 0; mt < 4; mt++)
                #pragma unroll
                for (int nt = 0; nt < 4; nt++) {
                    mma16816(c[mt][nt], ah[mt], bh[nt][0], bh[nt][1]);
                    mma16816(c[mt][nt], ah[mt], bl[nt][0], bl[nt][1]);
                    mma16816(c[mt][nt], al[mt], bh[nt][0], bh[nt][1]);
                }
        }
        if (ks + 1 < 32) {
            const int nxt = (ks + 1) & 1;
            #pragma unroll
            for (int t = 0; t < 8; t++) {
                const int p = t >> 1;
                const int ch = ((t & 1) << 8) | tid;
                const int row = ch >> 2;
                *(uint4*)(smem + nxt * STAGEB + p * PARTB + row * ROWB + ((ch & 3) << 4)) = stv[t];
            }
        }
        __syncthreads();
    }

    // Epilogue
    const int r0 = lid >> 2;
    const int c0 = (lid & 3) << 1;
    #pragma unroll
    for (int mt = 0; mt < 4; mt++) {
        #pragma unroll
        for (int nt = 0; nt < 4; nt++) {
            const int f = fb + wn * 32 + nt * 8 + c0;
            const float2 b2 = *(const float2*)(bias + f);
            const int tok0 = mb + wm * 64 + mt * 16 + r0;
            float2 v0 = make_float2(c[mt][nt][0] + b2.x, c[mt][nt][1] + b2.y);
            float2 v1 = make_float2(c[mt][nt][2] + b2.x, c[mt][nt][3] + b2.y);
            if (MODE == 0) {
                const int sec = f >> 10;
                const int cc = f & (PC - 1);
                const int hh = cc >> 6, d = cc & 63;
                float* dst = (sec == 0) ? g_q : (sec == 1) ? g_k : g_v;
                const int b = tok0 >> 11;
                const int tk = tok0 & (PT - 1);
                *(float2*)(dst + (((size_t)b * PH + hh) * PT + tk) * PDK + d) = v0;
                *(float2*)(dst + (((size_t)b * PH + hh) * PT + tk + 8) * PDK + d) = v1;
            } else {
                *(float2*)(outp + (size_t)tok0 * PC + f) = v0;
                *(float2*)(outp + (size_t)(tok0 + 8) * PC + f) = v1;
            }
        }
    }
}

// ---------------------------------------------------------------------------
// Flash attention (proven scalar version). Br=Bc=64, dk=64.
// ---------------------------------------------------------------------------
#define ATT_SMEM_FLOATS (64 * 68 * 2 + 64 * 64 * 2)

__global__ __launch_bounds__(256) void attn_kernel()
{
    extern __shared__ float sm[];
    float* Qt = sm;                 // [d][r], ld 68 (pre-scaled by 1/8)
    float* Kt = Qt + 64 * 68;       // [d][c], ld 68
    float* Vs = Kt + 64 * 68;       // [j][d], ld 64
    float* Pt = Vs + 64 * 64;       // [r][c], ld 64

    const int qt = blockIdx.x, hh = blockIdx.y, bidx = blockIdx.z;
    const float* qbase = g_q + (((size_t)bidx * PH + hh) * PT + qt * 64) * PDK;
    const float* kbase = g_k + (((size_t)bidx * PH + hh) * PT) * PDK;
    const float* vbase = g_v + (((size_t)bidx * PH + hh) * PT) * PDK;

    const int tid = threadIdx.x;
    const int tx = tid & 15, ty = tid >> 4;
    const int lj = tid >> 2;
    const int ld0 = (tid & 3) << 4;

    #pragma unroll
    for (int i = 0; i < 4; i++) {
        float4 t4 = *(const float4*)(qbase + (size_t)lj * PDK + ld0 + i * 4);
        const int d = ld0 + i * 4;
        Qt[(d + 0) * 68 + lj] = t4.x * 0.125f;
        Qt[(d + 1) * 68 + lj] = t4.y * 0.125f;
        Qt[(d + 2) * 68 + lj] = t4.z * 0.125f;
        Qt[(d + 3) * 68 + lj] = t4.w * 0.125f;
    }

    float mrow[4], lrow[4], o[4][4];
    #pragma unroll
    for (int i = 0; i < 4; i++) {
        mrow[i] = -CUDART_INF_F;
        lrow[i] = 0.0f;
        #pragma unroll
        for (int j = 0; j < 4; j++) o[i][j] = 0.0f;
    }

    for (int kt = 0; kt < PT / 64; kt++) {
        __syncthreads();
        #pragma unroll
        for (int i = 0; i < 4; i++) {
            float4 t4 = *(const float4*)(kbase + ((size_t)kt * 64 + lj) * PDK + ld0 + i * 4);
            const int d = ld0 + i * 4;
            Kt[(d + 0) * 68 + lj] = t4.x;
            Kt[(d + 1) * 68 + lj] = t4.y;
            Kt[(d + 2) * 68 + lj] = t4.z;
            Kt[(d + 3) * 68 + lj] = t4.w;
            float4 v4 = *(const float4*)(vbase + ((size_t)kt * 64 + lj) * PDK + ld0 + i * 4);
            *(float4*)&Vs[lj * 64 + ld0 + i * 4] = v4;
        }
        __syncthreads();

        float s[4][4] = {};
        #pragma unroll
        for (int d = 0; d < 64; d++) {
            float4 a4 = *(const float4*)&Qt[d * 68 + (ty << 2)];
            float4 b4 = *(const float4*)&Kt[d * 68 + (tx << 2)];
            float a[4] = {a4.x, a4.y, a4.z, a4.w};
            float b[4] = {b4.x, b4.y, b4.z, b4.w};
            #pragma unroll
            for (int i = 0; i < 4; i++)
                #pragma unroll
                for (int j = 0; j < 4; j++)
                    s[i][j] = fmaf(a[i], b[j], s[i][j]);
        }

        #pragma unroll
        for (int i = 0; i < 4; i++) {
            float mx = fmaxf(fmaxf(s[i][0], s[i][1]), fmaxf(s[i][2], s[i][3]));
            #pragma unroll
            for (int off = 8; off >= 1; off >>= 1)
                mx = fmaxf(mx, __shfl_xor_sync(0xffffffffu, mx, off));
            const float mnew = fmaxf(mrow[i], mx);
            const float alpha = __expf(mrow[i] - mnew);
            mrow[i] = mnew;
            float rs = 0.0f;
            #pragma unroll
            for (int j = 0; j < 4; j++) {
                const float p = __expf(s[i][j] - mnew);
                s[i][j] = p;
                rs += p;
            }
            #pragma unroll
            for (int off = 8; off >= 1; off >>= 1)
                rs += __shfl_xor_sync(0xffffffffu, rs, off);
            lrow[i] = lrow[i] * alpha + rs;
            #pragma unroll
            for (int j = 0; j < 4; j++) o[i][j] *= alpha;
        }

        #pragma unroll
        for (int i = 0; i < 4; i++) {
            float4 p4 = make_float4(s[i][0], s[i][1], s[i][2], s[i][3]);
            *(float4*)&Pt[((ty << 2) + i) * 64 + (tx << 2)] = p4;
        }
        __syncthreads();

        #pragma unroll
        for (int j = 0; j < 64; j++) {
            float4 v4 = *(const float4*)&Vs[j * 64 + (tx << 2)];
            float v[4] = {v4.x, v4.y, v4.z, v4.w};
            float p0 = Pt[((ty << 2) + 0) * 64 + j];
            float p1 = Pt[((ty << 2) + 1) * 64 + j];
            float p2 = Pt[((ty << 2) + 2) * 64 + j];
            float p3 = Pt[((ty << 2) + 3) * 64 + j];
            #pragma unroll
            for (int cc = 0; cc < 4; cc++) {
                o[0][cc] = fmaf(p0, v[cc], o[0][cc]);
                o[1][cc] = fmaf(p1, v[cc], o[1][cc]);
                o[2][cc] = fmaf(p2, v[cc], o[2][cc]);
                o[3][cc] = fmaf(p3, v[cc], o[3][cc]);
            }
        }
    }

    #pragma unroll
    for (int i = 0; i < 4; i++) {
        const float inv = 1.0f / lrow[i];
        const int tok = qt * 64 + (ty << 2) + i;
        float4 r4 = make_float4(o[i][0] * inv, o[i][1] * inv, o[i][2] * inv, o[i][3] * inv);
        *(float4*)&g_y[((size_t)bidx * PT + tok) * PC + hh * PDK + (tx << 2)] = r4;
    }
}

// ---------------------------------------------------------------------------
extern "C" void kernel_launch(void* const* d_in, const int* in_sizes, int n_in,
                              void* d_out, int out_size)
{
    const float* x      = (const float*)d_in[0];
    const float* w_attn = (const float*)d_in[1];
    const float* b_attn = (const float*)d_in[2];
    const float* w_proj = (const float*)d_in[3];
    const float* b_proj = (const float*)d_in[4];
    float* out = (float*)d_out;

    cudaFuncSetAttribute(tc_gemm_kernel<0>,
                         cudaFuncAttributeMaxDynamicSharedMemorySize, GK_SMEM);
    cudaFuncSetAttribute(tc_gemm_kernel<1>,
                         cudaFuncAttributeMaxDynamicSharedMemorySize, GK_SMEM);
    cudaFuncSetAttribute(attn_kernel,
                         cudaFuncAttributeMaxDynamicSharedMemorySize,
                         ATT_SMEM_FLOATS * 4);

    __nv_bfloat16 *xh, *xl, *yh, *yl, *wah, *wal, *wph, *wpl;
    cudaGetSymbolAddress((void**)&xh, g_xh);  cudaGetSymbolAddress((void**)&xl, g_xl);
    cudaGetSymbolAddress((void**)&yh, g_yh);  cudaGetSymbolAddress((void**)&yl, g_yl);
    cudaGetSymbolAddress((void**)&wah, g_wah); cudaGetSymbolAddress((void**)&wal, g_wal);
    cudaGetSymbolAddress((void**)&wph, g_wph); cudaGetSymbolAddress((void**)&wpl, g_wpl);
    float* y; cudaGetSymbolAddress((void**)&y, g_y);

    // Split-convert inputs
    conv_split_kernel<<<NTOK * PC / 1024, 256>>>(x, xh, xl);
    conv_split_kernel<<<M3 * PC / 1024, 256>>>(w_attn, wah, wal);
    conv_split_kernel<<<PC * PC / 1024, 256>>>(w_proj, wph, wpl);

    // QKV GEMM: tokens x 3072 features
    tc_gemm_kernel<0><<<dim3(M3 / 128, NTOK / 128), 256, GK_SMEM>>>(
        xh, xl, wah, wal, b_attn, nullptr);

    attn_kernel<<<dim3(PT / 64, PH, PB), 256, ATT_SMEM_FLOATS * 4>>>();

    conv_split_kernel<<<NTOK * PC / 1024, 256>>>(y, yh, yl);

    // Proj GEMM: tokens x 1024 features
    tc_gemm_kernel<1><<<dim3(PC / 128, NTOK / 128), 256, GK_SMEM>>>(
        yh, yl, wph, wpl, b_proj, out);
}

// round 7
// speedup vs baseline: 2.8883x; 1.9238x over previous
#include <cuda_runtime.h>
#include <cuda_bf16.h>
#include <math_constants.h>
#include <cstdint>

// Problem constants
#define PB 4
#define PT 2048
#define PC 1024
#define PH 16
#define PDK 64
#define NTOK (PB * PT)      // 8192
#define M3 (3 * PC)         // 3072

// fp32 scratch
__device__ float g_q[NTOK * PC];
__device__ float g_k[NTOK * PC];
__device__ float g_v[NTOK * PC];
__device__ float g_y[NTOK * PC];
// bf16 split planes
__device__ __nv_bfloat16 g_xh[NTOK * PC], g_xl[NTOK * PC];
__device__ __nv_bfloat16 g_yh[NTOK * PC], g_yl[NTOK * PC];
__device__ __nv_bfloat16 g_wah[M3 * PC],  g_wal[M3 * PC];
__device__ __nv_bfloat16 g_wph[PC * PC],  g_wpl[PC * PC];

// ---------------------------------------------------------------------------
// Split-convert: fp32 -> (hi bf16, lo bf16), lo = x - (float)hi
// ---------------------------------------------------------------------------
__global__ __launch_bounds__(256) void conv_split_kernel(
    const float* __restrict__ src, __nv_bfloat16* __restrict__ hi,
    __nv_bfloat16* __restrict__ lo)
{
    const int i = (blockIdx.x * 256 + threadIdx.x) * 4;
    float4 v = *(const float4*)(src + i);
    __nv_bfloat162 h0 = __floats2bfloat162_rn(v.x, v.y);
    __nv_bfloat162 h1 = __floats2bfloat162_rn(v.z, v.w);
    __nv_bfloat162 l0 = __floats2bfloat162_rn(v.x - __bfloat162float(h0.x),
                                              v.y - __bfloat162float(h0.y));
    __nv_bfloat162 l1 = __floats2bfloat162_rn(v.z - __bfloat162float(h1.x),
                                              v.w - __bfloat162float(h1.y));
    *(uint2*)(hi + i) = make_uint2(*(const uint32_t*)&h0, *(const uint32_t*)&h1);
    *(uint2*)(lo + i) = make_uint2(*(const uint32_t*)&l0, *(const uint32_t*)&l1);
}

// ---------------------------------------------------------------------------
// Common HMMA helpers
// ---------------------------------------------------------------------------
__device__ __forceinline__ uint32_t smem_u32(const void* p) {
    uint32_t a;
    asm("{ .reg .u64 t; cvta.to.shared.u64 t, %1; cvt.u32.u64 %0, t; }"
        : "=r"(a) : "l"(p));
    return a;
}
__device__ __forceinline__ void ldsm_x4(uint32_t addr, uint32_t& r0, uint32_t& r1,
                                        uint32_t& r2, uint32_t& r3) {
    asm volatile("ldmatrix.sync.aligned.m8n8.x4.shared.b16 {%0,%1,%2,%3}, [%4];"
                 : "=r"(r0), "=r"(r1), "=r"(r2), "=r"(r3) : "r"(addr));
}
__device__ __forceinline__ void ldsm_x4t(uint32_t addr, uint32_t& r0, uint32_t& r1,
                                         uint32_t& r2, uint32_t& r3) {
    asm volatile("ldmatrix.sync.aligned.m8n8.x4.trans.shared.b16 {%0,%1,%2,%3}, [%4];"
                 : "=r"(r0), "=r"(r1), "=r"(r2), "=r"(r3) : "r"(addr));
}
__device__ __forceinline__ void mma16816(float* c, const uint32_t* a,
                                         uint32_t b0, uint32_t b1) {
    asm volatile(
        "mma.sync.aligned.m16n8k16.row.col.f32.bf16.bf16.f32 "
        "{%0,%1,%2,%3}, {%4,%5,%6,%7}, {%8,%9}, {%0,%1,%2,%3};"
        : "+f"(c[0]), "+f"(c[1]), "+f"(c[2]), "+f"(c[3])
        : "r"(a[0]), "r"(a[1]), "r"(a[2]), "r"(a[3]), "r"(b0), "r"(b1));
}
__device__ __forceinline__ void pack_split(float a, float b, uint32_t& hi, uint32_t& lo) {
    __nv_bfloat162 h = __floats2bfloat162_rn(a, b);
    __nv_bfloat162 l = __floats2bfloat162_rn(a - __bfloat162float(h.x),
                                             b - __bfloat162float(h.y));
    hi = *(const uint32_t*)&h;
    lo = *(const uint32_t*)&l;
}
__device__ __forceinline__ void split_store8(char* ph, char* pl, uint32_t off, float4 v) {
    __nv_bfloat162 h0 = __floats2bfloat162_rn(v.x, v.y);
    __nv_bfloat162 h1 = __floats2bfloat162_rn(v.z, v.w);
    __nv_bfloat162 l0 = __floats2bfloat162_rn(v.x - __bfloat162float(h0.x),
                                              v.y - __bfloat162float(h0.y));
    __nv_bfloat162 l1 = __floats2bfloat162_rn(v.z - __bfloat162float(h1.x),
                                              v.w - __bfloat162float(h1.y));
    *(uint2*)(ph + off) = make_uint2(*(const uint32_t*)&h0, *(const uint32_t*)&h1);
    *(uint2*)(pl + off) = make_uint2(*(const uint32_t*)&l0, *(const uint32_t*)&l1);
}

// ---------------------------------------------------------------------------
// Tensor-core dense GEMM (same as R4 — passed): D[m=token][n=feature]
// ---------------------------------------------------------------------------
#define ROWB 80
#define PARTB (128 * ROWB)
#define STAGEB (4 * PARTB)
#define GK_SMEM (2 * STAGEB)        // 81920

template <int MODE>
__global__ __launch_bounds__(256) void tc_gemm_kernel(
    const __nv_bfloat16* __restrict__ Ah_g, const __nv_bfloat16* __restrict__ Al_g,
    const __nv_bfloat16* __restrict__ Bh_g, const __nv_bfloat16* __restrict__ Bl_g,
    const float* __restrict__ bias, float* __restrict__ outp)
{
    extern __shared__ __align__(16) char smem[];
    const uint32_t sbase = smem_u32(smem);
    const int tid = threadIdx.x;
    const int wid = tid >> 5, lid = tid & 31;
    const int wm = wid >> 2, wn = wid & 3;
    const int fb = blockIdx.x * 128;
    const int mb = blockIdx.y * 128;

    const __nv_bfloat16* srcs[4] = {
        Ah_g + (size_t)mb * PC, Al_g + (size_t)mb * PC,
        Bh_g + (size_t)fb * PC, Bl_g + (size_t)fb * PC };

    float c[4][4][4];
    #pragma unroll
    for (int i = 0; i < 4; i++)
        #pragma unroll
        for (int j = 0; j < 4; j++)
            #pragma unroll
            for (int e = 0; e < 4; e++) c[i][j][e] = 0.0f;

    #pragma unroll
    for (int t = 0; t < 8; t++) {
        const int p = t >> 1;
        const int ch = ((t & 1) << 8) | tid;
        const int row = ch >> 2, kq = (ch & 3) << 3;
        uint4 v = *(const uint4*)(srcs[p] + (size_t)row * PC + kq);
        *(uint4*)(smem + p * PARTB + row * ROWB + ((ch & 3) << 4)) = v;
    }
    __syncthreads();

    const int lr = lid & 15;
    const int lk2 = ((lid >> 4) << 3) * 2;

    for (int ks = 0; ks < 32; ks++) {
        const int cur = ks & 1;
        uint4 stv[8];
        if (ks + 1 < 32) {
            const int kh = (ks + 1) * 32;
            #pragma unroll
            for (int t = 0; t < 8; t++) {
                const int p = t >> 1;
                const int ch = ((t & 1) << 8) | tid;
                const int row = ch >> 2, kq = (ch & 3) << 3;
                stv[t] = *(const uint4*)(srcs[p] + (size_t)row * PC + kh + kq);
            }
        }
        const uint32_t stb = sbase + cur * STAGEB;
        #pragma unroll
        for (int k16 = 0; k16 < 2; k16++) {
            const uint32_t kb = k16 * 32 + lk2;
            uint32_t ah[4][4], al[4][4];
            #pragma unroll
            for (int mt = 0; mt < 4; mt++) {
                const uint32_t ra = (wm * 64 + mt * 16 + lr) * ROWB + kb;
                ldsm_x4(stb + 0 * PARTB + ra, ah[mt][0], ah[mt][1], ah[mt][2], ah[mt][3]);
                ldsm_x4(stb + 1 * PARTB + ra, al[mt][0], al[mt][1], al[mt][2], al[mt][3]);
            }
            uint32_t bh[4][2], bl[4][2];
            #pragma unroll
            for (int np = 0; np < 2; np++) {
                const uint32_t rb = (wn * 32 + np * 16 + lr) * ROWB + kb;
                uint32_t r0, r1, r2, r3;
                ldsm_x4(stb + 2 * PARTB + rb, r0, r1, r2, r3);
                bh[np * 2][0] = r0; bh[np * 2][1] = r2;
                bh[np * 2 + 1][0] = r1; bh[np * 2 + 1][1] = r3;
                ldsm_x4(stb + 3 * PARTB + rb, r0, r1, r2, r3);
                bl[np * 2][0] = r0; bl[np * 2][1] = r2;
                bl[np * 2 + 1][0] = r1; bl[np * 2 + 1][1] = r3;
            }
            #pragma unroll
            for (int mt = 0; mt < 4; mt++)
                #pragma unroll
                for (int nt = 0; nt < 4; nt++) {
                    mma16816(c[mt][nt], ah[mt], bh[nt][0], bh[nt][1]);
                    mma16816(c[mt][nt], ah[mt], bl[nt][0], bl[nt][1]);
                    mma16816(c[mt][nt], al[mt], bh[nt][0], bh[nt][1]);
                }
        }
        if (ks + 1 < 32) {
            const int nxt = (ks + 1) & 1;
            #pragma unroll
            for (int t = 0; t < 8; t++) {
                const int p = t >> 1;
                const int ch = ((t & 1) << 8) | tid;
                const int row = ch >> 2;
                *(uint4*)(smem + nxt * STAGEB + p * PARTB + row * ROWB + ((ch & 3) << 4)) = stv[t];
            }
        }
        __syncthreads();
    }

    const int r0 = lid >> 2;
    const int c0 = (lid & 3) << 1;
    #pragma unroll
    for (int mt = 0; mt < 4; mt++) {
        #pragma unroll
        for (int nt = 0; nt < 4; nt++) {
            const int f = fb + wn * 32 + nt * 8 + c0;
            const float2 b2 = *(const float2*)(bias + f);
            const int tok0 = mb + wm * 64 + mt * 16 + r0;
            float2 v0 = make_float2(c[mt][nt][0] + b2.x, c[mt][nt][1] + b2.y);
            float2 v1 = make_float2(c[mt][nt][2] + b2.x, c[mt][nt][3] + b2.y);
            if (MODE == 0) {
                const int sec = f >> 10;
                const int cc = f & (PC - 1);
                const int hh = cc >> 6, d = cc & 63;
                float* dst = (sec == 0) ? g_q : (sec == 1) ? g_k : g_v;
                const int b = tok0 >> 11;
                const int tk = tok0 & (PT - 1);
                *(float2*)(dst + (((size_t)b * PH + hh) * PT + tk) * PDK + d) = v0;
                *(float2*)(dst + (((size_t)b * PH + hh) * PT + tk + 8) * PDK + d) = v1;
            } else {
                *(float2*)(outp + (size_t)tok0 * PC + f) = v0;
                *(float2*)(outp + (size_t)(tok0 + 8) * PC + f) = v1;
            }
        }
    }
}

// ---------------------------------------------------------------------------
// Tensor-core flash attention. Br=128 (8 warps x 16 rows), Bc=64, dk=64.
// Q/K/V split-bf16 in smem; S and P in registers; V via ldmatrix.trans.
// ---------------------------------------------------------------------------
#define AROW 72                     // halves per smem row (144B, conflict-free)
#define AROWB 144
#define AQH 0
#define AQL 18432                   // 128*144
#define AKH 36864
#define AKL 46080                   // +64*144
#define AVH 55296
#define AVL 64512
#define ATT_SMEM 73728

__global__ __launch_bounds__(256) void attn_tc_kernel()
{
    extern __shared__ __align__(16) char smem[];
    const uint32_t sb = smem_u32(smem);
    const int tid = threadIdx.x, wid = tid >> 5, lid = tid & 31;
    const int qt = blockIdx.x, hh = blockIdx.y, bidx = blockIdx.z;
    const float* qbase = g_q + (((size_t)bidx * PH + hh) * PT + qt * 128) * PDK;
    const float* kbase = g_k + ((size_t)bidx * PH + hh) * PT * PDK;
    const float* vbase = g_v + ((size_t)bidx * PH + hh) * PT * PDK;

    // Load Q (128x64), scaled by 1/8, split into hi/lo planes.
    #pragma unroll
    for (int it = 0; it < 8; it++) {
        const int flat = it * 256 + tid;
        const int r = flat >> 4, d4 = (flat & 15) << 2;
        float4 v = *(const float4*)(qbase + (size_t)r * PDK + d4);
        v.x *= 0.125f; v.y *= 0.125f; v.z *= 0.125f; v.w *= 0.125f;
        split_store8(smem + AQH, smem + AQL, (uint32_t)(r * AROWB + d4 * 2), v);
    }

    float oc[8][4];
    #pragma unroll
    for (int nt = 0; nt < 8; nt++)
        #pragma unroll
        for (int e = 0; e < 4; e++) oc[nt][e] = 0.0f;
    float mrow[2] = {-CUDART_INF_F, -CUDART_INF_F};
    float lrow[2] = {0.0f, 0.0f};

    const int lr = lid & 15, lh = lid >> 4;

    for (int kt = 0; kt < PT / 64; kt++) {
        __syncthreads();
        // Load K and V tiles (64x64 each), split.
        #pragma unroll
        for (int it = 0; it < 4; it++) {
            const int flat = it * 256 + tid;
            const int j = flat >> 4, d4 = (flat & 15) << 2;
            const uint32_t off = (uint32_t)(j * AROWB + d4 * 2);
            float4 kv = *(const float4*)(kbase + ((size_t)kt * 64 + j) * PDK + d4);
            split_store8(smem + AKH, smem + AKL, off, kv);
            float4 vv = *(const float4*)(vbase + ((size_t)kt * 64 + j) * PDK + d4);
            split_store8(smem + AVH, smem + AVL, off, vv);
        }
        __syncthreads();

        // S = Q K^T  (per warp: 16 rows x 64 cols)
        float sc[8][4];
        #pragma unroll
        for (int nt = 0; nt < 8; nt++)
            #pragma unroll
            for (int e = 0; e < 4; e++) sc[nt][e] = 0.0f;
        #pragma unroll
        for (int k16 = 0; k16 < 4; k16++) {
            const uint32_t colb = (uint32_t)((k16 * 16 + lh * 8) * 2);
            uint32_t aqh[4], aql[4];
            const uint32_t qra = (uint32_t)((wid * 16 + lr) * AROWB) + colb;
            ldsm_x4(sb + AQH + qra, aqh[0], aqh[1], aqh[2], aqh[3]);
            ldsm_x4(sb + AQL + qra, aql[0], aql[1], aql[2], aql[3]);
            #pragma unroll
            for (int np = 0; np < 4; np++) {
                const uint32_t kra = (uint32_t)((np * 16 + lr) * AROWB) + colb;
                uint32_t h0, h1, h2, h3, l0, l1, l2, l3;
                ldsm_x4(sb + AKH + kra, h0, h1, h2, h3);
                ldsm_x4(sb + AKL + kra, l0, l1, l2, l3);
                mma16816(sc[2 * np], aqh, h0, h2);
                mma16816(sc[2 * np], aqh, l0, l2);
                mma16816(sc[2 * np], aql, h0, h2);
                mma16816(sc[2 * np + 1], aqh, h1, h3);
                mma16816(sc[2 * np + 1], aqh, l1, l3);
                mma16816(sc[2 * np + 1], aql, h1, h3);
            }
        }

        // Online softmax; rows r0 = lid>>2 (+8). 4 lanes per row -> shfl 1,2.
        #pragma unroll
        for (int i = 0; i < 2; i++) {
            float mx = -CUDART_INF_F;
            #pragma unroll
            for (int nt = 0; nt < 8; nt++)
                mx = fmaxf(mx, fmaxf(sc[nt][2 * i], sc[nt][2 * i + 1]));
            mx = fmaxf(mx, __shfl_xor_sync(0xffffffffu, mx, 1));
            mx = fmaxf(mx, __shfl_xor_sync(0xffffffffu, mx, 2));
            const float mnew = fmaxf(mrow[i], mx);
            const float alpha = __expf(mrow[i] - mnew);
            mrow[i] = mnew;
            float rs = 0.0f;
            #pragma unroll
            for (int nt = 0; nt < 8; nt++) {
                const float p0 = __expf(sc[nt][2 * i] - mnew);
                const float p1 = __expf(sc[nt][2 * i + 1] - mnew);
                sc[nt][2 * i] = p0; sc[nt][2 * i + 1] = p1;
                rs += p0 + p1;
            }
            rs += __shfl_xor_sync(0xffffffffu, rs, 1);
            rs += __shfl_xor_sync(0xffffffffu, rs, 2);
            lrow[i] = lrow[i] * alpha + rs;
            #pragma unroll
            for (int nt = 0; nt < 8; nt++) {
                oc[nt][2 * i] *= alpha;
                oc[nt][2 * i + 1] *= alpha;
            }
        }

        // O += P V   (P from registers, V via ldmatrix.trans)
        #pragma unroll
        for (int j16 = 0; j16 < 4; j16++) {
            uint32_t aph[4], apl[4];
            pack_split(sc[2 * j16][0], sc[2 * j16][1], aph[0], apl[0]);
            pack_split(sc[2 * j16][2], sc[2 * j16][3], aph[1], apl[1]);
            pack_split(sc[2 * j16 + 1][0], sc[2 * j16 + 1][1], aph[2], apl[2]);
            pack_split(sc[2 * j16 + 1][2], sc[2 * j16 + 1][3], aph[3], apl[3]);
            #pragma unroll
            for (int dp = 0; dp < 4; dp++) {
                const uint32_t vra = (uint32_t)((j16 * 16 + lr) * AROWB
                                                + (dp * 16 + lh * 8) * 2);
                uint32_t h0, h1, h2, h3, l0, l1, l2, l3;
                ldsm_x4t(sb + AVH + vra, h0, h1, h2, h3);
                ldsm_x4t(sb + AVL + vra, l0, l1, l2, l3);
                mma16816(oc[2 * dp], aph, h0, h1);
                mma16816(oc[2 * dp], aph, l0, l1);
                mma16816(oc[2 * dp], apl, h0, h1);
                mma16816(oc[2 * dp + 1], aph, h2, h3);
                mma16816(oc[2 * dp + 1], aph, l2, l3);
                mma16816(oc[2 * dp + 1], apl, h2, h3);
            }
        }
    }

    // Epilogue: normalize, write y[B,T,C]
    const int r0 = lid >> 2, c0 = (lid & 3) << 1;
    #pragma unroll
    for (int i = 0; i < 2; i++) {
        const float inv = 1.0f / lrow[i];
        const int tok = qt * 128 + wid * 16 + r0 + i * 8;
        float* dst = g_y + ((size_t)bidx * PT + tok) * PC + hh * PDK;
        #pragma unroll
        for (int nt = 0; nt < 8; nt++) {
            float2 v = make_float2(oc[nt][2 * i] * inv, oc[nt][2 * i + 1] * inv);
            *(float2*)(dst + nt * 8 + c0) = v;
        }
    }
}

// ---------------------------------------------------------------------------
extern "C" void kernel_launch(void* const* d_in, const int* in_sizes, int n_in,
                              void* d_out, int out_size)
{
    const float* x      = (const float*)d_in[0];
    const float* w_attn = (const float*)d_in[1];
    const float* b_attn = (const float*)d_in[2];
    const float* w_proj = (const float*)d_in[3];
    const float* b_proj = (const float*)d_in[4];
    float* out = (float*)d_out;

    cudaFuncSetAttribute(tc_gemm_kernel<0>,
                         cudaFuncAttributeMaxDynamicSharedMemorySize, GK_SMEM);
    cudaFuncSetAttribute(tc_gemm_kernel<1>,
                         cudaFuncAttributeMaxDynamicSharedMemorySize, GK_SMEM);
    cudaFuncSetAttribute(attn_tc_kernel,
                         cudaFuncAttributeMaxDynamicSharedMemorySize, ATT_SMEM);

    __nv_bfloat16 *xh, *xl, *yh, *yl, *wah, *wal, *wph, *wpl;
    cudaGetSymbolAddress((void**)&xh, g_xh);  cudaGetSymbolAddress((void**)&xl, g_xl);
    cudaGetSymbolAddress((void**)&yh, g_yh);  cudaGetSymbolAddress((void**)&yl, g_yl);
    cudaGetSymbolAddress((void**)&wah, g_wah); cudaGetSymbolAddress((void**)&wal, g_wal);
    cudaGetSymbolAddress((void**)&wph, g_wph); cudaGetSymbolAddress((void**)&wpl, g_wpl);
    float* y; cudaGetSymbolAddress((void**)&y, g_y);

    conv_split_kernel<<<NTOK * PC / 1024, 256>>>(x, xh, xl);
    conv_split_kernel<<<M3 * PC / 1024, 256>>>(w_attn, wah, wal);
    conv_split_kernel<<<PC * PC / 1024, 256>>>(w_proj, wph, wpl);

    tc_gemm_kernel<0><<<dim3(M3 / 128, NTOK / 128), 256, GK_SMEM>>>(
        xh, xl, wah, wal, b_attn, nullptr);

    attn_tc_kernel<<<dim3(PT / 128, PH, PB), 256, ATT_SMEM>>>();

    conv_split_kernel<<<NTOK * PC / 1024, 256>>>(y, yh, yl);

    tc_gemm_kernel<1><<<dim3(PC / 128, NTOK / 128), 256, GK_SMEM>>>(
        yh, yl, wph, wpl, b_proj, out);
}

// round 11
// speedup vs baseline: 3.4664x; 1.2001x over previous
#include <cuda_runtime.h>
#include <cuda_bf16.h>
#include <math_constants.h>
#include <cstdint>

// Problem constants
#define PB 4
#define PT 2048
#define PC 1024
#define PH 16
#define PDK 64
#define NTOK (PB * PT)      // 8192
#define M3 (3 * PC)         // 3072

// bf16 split planes (q pre-scaled by 1/8)
__device__ __nv_bfloat16 g_xh[NTOK * PC], g_xl[NTOK * PC];
__device__ __nv_bfloat16 g_yh[NTOK * PC], g_yl[NTOK * PC];
__device__ __nv_bfloat16 g_wah[M3 * PC],  g_wal[M3 * PC];
__device__ __nv_bfloat16 g_wph[PC * PC],  g_wpl[PC * PC];
__device__ __nv_bfloat16 g_qh[NTOK * PC], g_ql[NTOK * PC];
__device__ __nv_bfloat16 g_kh[NTOK * PC], g_kl[NTOK * PC];
__device__ __nv_bfloat16 g_vh[NTOK * PC], g_vl[NTOK * PC];

// ---------------------------------------------------------------------------
// Helpers
// ---------------------------------------------------------------------------
__device__ __forceinline__ uint32_t smem_u32(const void* p) {
    uint32_t a;
    asm("{ .reg .u64 t; cvta.to.shared.u64 t, %1; cvt.u32.u64 %0, t; }"
        : "=r"(a) : "l"(p));
    return a;
}
__device__ __forceinline__ void cp16(uint32_t dst, const void* src) {
    asm volatile("cp.async.cg.shared.global [%0], [%1], 16;"
                 :: "r"(dst), "l"(src));
}
#define CP_COMMIT() asm volatile("cp.async.commit_group;" ::: "memory")
#define CP_WAIT(n)  asm volatile("cp.async.wait_group %0;" :: "n"(n) : "memory")

__device__ __forceinline__ void ldsm_x4(uint32_t addr, uint32_t& r0, uint32_t& r1,
                                        uint32_t& r2, uint32_t& r3) {
    asm volatile("ldmatrix.sync.aligned.m8n8.x4.shared.b16 {%0,%1,%2,%3}, [%4];"
                 : "=r"(r0), "=r"(r1), "=r"(r2), "=r"(r3) : "r"(addr));
}
__device__ __forceinline__ void ldsm_x4t(uint32_t addr, uint32_t& r0, uint32_t& r1,
                                         uint32_t& r2, uint32_t& r3) {
    asm volatile("ldmatrix.sync.aligned.m8n8.x4.trans.shared.b16 {%0,%1,%2,%3}, [%4];"
                 : "=r"(r0), "=r"(r1), "=r"(r2), "=r"(r3) : "r"(addr));
}
__device__ __forceinline__ void mma16816(float* c, const uint32_t* a,
                                         uint32_t b0, uint32_t b1) {
    asm volatile(
        "mma.sync.aligned.m16n8k16.row.col.f32.bf16.bf16.f32 "
        "{%0,%1,%2,%3}, {%4,%5,%6,%7}, {%8,%9}, {%0,%1,%2,%3};"
        : "+f"(c[0]), "+f"(c[1]), "+f"(c[2]), "+f"(c[3])
        : "r"(a[0]), "r"(a[1]), "r"(a[2]), "r"(a[3]), "r"(b0), "r"(b1));
}
__device__ __forceinline__ void pack_split(float a, float b, uint32_t& hi, uint32_t& lo) {
    __nv_bfloat162 h = __floats2bfloat162_rn(a, b);
    __nv_bfloat162 l = __floats2bfloat162_rn(a - __bfloat162float(h.x),
                                             b - __bfloat162float(h.y));
    hi = *(const uint32_t*)&h;
    lo = *(const uint32_t*)&l;
}

// ---------------------------------------------------------------------------
// Split-convert: fp32 -> (hi bf16, lo bf16)
// ---------------------------------------------------------------------------
__global__ __launch_bounds__(256) void conv_split_kernel(
    const float* __restrict__ src, __nv_bfloat16* __restrict__ hi,
    __nv_bfloat16* __restrict__ lo)
{
    const int i = (blockIdx.x * 256 + threadIdx.x) * 4;
    float4 v = *(const float4*)(src + i);
    __nv_bfloat162 h0 = __floats2bfloat162_rn(v.x, v.y);
    __nv_bfloat162 h1 = __floats2bfloat162_rn(v.z, v.w);
    __nv_bfloat162 l0 = __floats2bfloat162_rn(v.x - __bfloat162float(h0.x),
                                              v.y - __bfloat162float(h0.y));
    __nv_bfloat162 l1 = __floats2bfloat162_rn(v.z - __bfloat162float(h1.x),
                                              v.w - __bfloat162float(h1.y));
    *(uint2*)(hi + i) = make_uint2(*(const uint32_t*)&h0, *(const uint32_t*)&h1);
    *(uint2*)(lo + i) = make_uint2(*(const uint32_t*)&l0, *(const uint32_t*)&l1);
}

// ---------------------------------------------------------------------------
// Tensor-core dense GEMM, cp.async double-buffered, 2 CTAs/SM.
// D[m=token][n=feature] = A * B^T + bias; A,B hi/lo bf16 planes k-major.
// MODE 0: write q/k/v split planes (q scaled 1/8). MODE 1: write fp32 out.
// ---------------------------------------------------------------------------
#define ROWB 80
#define PARTB (128 * ROWB)
#define STAGEB (4 * PARTB)
#define GK_SMEM (2 * STAGEB)        // 81920

__device__ __forceinline__ void gk_issue(
    const __nv_bfloat16* const* srcs, uint32_t sbase, int st, int ks, int tid)
{
    #pragma unroll
    for (int t = 0; t < 8; t++) {
        const int p = t >> 1;
        const int ch = ((t & 1) << 8) | tid;
        const int row = ch >> 2, q = ch & 3;
        cp16(sbase + st * STAGEB + p * PARTB + row * ROWB + (q << 4),
             srcs[p] + (size_t)row * PC + ks * 32 + q * 8);
    }
}

template <int MODE>
__global__ __launch_bounds__(256, 2) void tc_gemm_kernel(
    const __nv_bfloat16* __restrict__ Ah_g, const __nv_bfloat16* __restrict__ Al_g,
    const __nv_bfloat16* __restrict__ Bh_g, const __nv_bfloat16* __restrict__ Bl_g,
    const float* __restrict__ bias, float* __restrict__ outp)
{
    extern __shared__ __align__(16) char smem[];
    const uint32_t sbase = smem_u32(smem);
    const int tid = threadIdx.x;
    const int wid = tid >> 5, lid = tid & 31;
    const int wm = wid >> 2, wn = wid & 3;
    const int fb = blockIdx.x * 128;
    const int mb = blockIdx.y * 128;

    const __nv_bfloat16* srcs[4] = {
        Ah_g + (size_t)mb * PC, Al_g + (size_t)mb * PC,
        Bh_g + (size_t)fb * PC, Bl_g + (size_t)fb * PC };

    float c[4][4][4];
    #pragma unroll
    for (int i = 0; i < 4; i++)
        #pragma unroll
        for (int j = 0; j < 4; j++)
            #pragma unroll
            for (int e = 0; e < 4; e++) c[i][j][e] = 0.0f;

    gk_issue(srcs, sbase, 0, 0, tid);
    CP_COMMIT();

    const int lr = lid & 15;
    const int lk2 = ((lid >> 4) << 3) * 2;

    for (int ks = 0; ks < 32; ks++) {
        const int cur = ks & 1;
        if (ks + 1 < 32) {
            gk_issue(srcs, sbase, (ks + 1) & 1, ks + 1, tid);
            CP_COMMIT();
            CP_WAIT(1);
        } else {
            CP_WAIT(0);
        }
        __syncthreads();

        const uint32_t stb = sbase + cur * STAGEB;
        #pragma unroll
        for (int k16 = 0; k16 < 2; k16++) {
            const uint32_t kb = k16 * 32 + lk2;
            uint32_t ah[4][4], al[4][4];
            #pragma unroll
            for (int mt = 0; mt < 4; mt++) {
                const uint32_t ra = (wm * 64 + mt * 16 + lr) * ROWB + kb;
                ldsm_x4(stb + 0 * PARTB + ra, ah[mt][0], ah[mt][1], ah[mt][2], ah[mt][3]);
                ldsm_x4(stb + 1 * PARTB + ra, al[mt][0], al[mt][1], al[mt][2], al[mt][3]);
            }
            uint32_t bh[4][2], bl[4][2];
            #pragma unroll
            for (int np = 0; np < 2; np++) {
                const uint32_t rb = (wn * 32 + np * 16 + lr) * ROWB + kb;
                uint32_t r0, r1, r2, r3;
                ldsm_x4(stb + 2 * PARTB + rb, r0, r1, r2, r3);
                bh[np * 2][0] = r0; bh[np * 2][1] = r2;
                bh[np * 2 + 1][0] = r1; bh[np * 2 + 1][1] = r3;
                ldsm_x4(stb + 3 * PARTB + rb, r0, r1, r2, r3);
                bl[np * 2][0] = r0; bl[np * 2][1] = r2;
                bl[np * 2 + 1][0] = r1; bl[np * 2 + 1][1] = r3;
            }
            #pragma unroll
            for (int mt = 0; mt < 4; mt++)
                #pragma unroll
                for (int nt = 0; nt < 4; nt++) {
                    mma16816(c[mt][nt], ah[mt], bh[nt][0], bh[nt][1]);
                    mma16816(c[mt][nt], ah[mt], bl[nt][0], bl[nt][1]);
                    mma16816(c[mt][nt], al[mt], bh[nt][0], bh[nt][1]);
                }
        }
        __syncthreads();
    }

    const int r0 = lid >> 2;
    const int c0 = (lid & 3) << 1;
    #pragma unroll
    for (int mt = 0; mt < 4; mt++) {
        #pragma unroll
        for (int nt = 0; nt < 4; nt++) {
            const int f = fb + wn * 32 + nt * 8 + c0;
            const float2 b2 = *(const float2*)(bias + f);
            const int tok0 = mb + wm * 64 + mt * 16 + r0;
            float2 v0 = make_float2(c[mt][nt][0] + b2.x, c[mt][nt][1] + b2.y);
            float2 v1 = make_float2(c[mt][nt][2] + b2.x, c[mt][nt][3] + b2.y);
            if (MODE == 0) {
                const int sec = f >> 10;
                const int cc = f & (PC - 1);
                const int hh = cc >> 6, d = cc & 63;
                __nv_bfloat16 *dh, *dl;
                float sc = 1.0f;
                if (sec == 0) { dh = g_qh; dl = g_ql; sc = 0.125f; }
                else if (sec == 1) { dh = g_kh; dl = g_kl; }
                else { dh = g_vh; dl = g_vl; }
                const int b = tok0 >> 11;
                const int tk = tok0 & (PT - 1);
                const size_t base = (((size_t)b * PH + hh) * PT + tk) * PDK + d;
                uint32_t h, l;
                pack_split(v0.x * sc, v0.y * sc, h, l);
                *(uint32_t*)(dh + base) = h;
                *(uint32_t*)(dl + base) = l;
                pack_split(v1.x * sc, v1.y * sc, h, l);
                *(uint32_t*)(dh + base + 8 * PDK) = h;
                *(uint32_t*)(dl + base + 8 * PDK) = l;
            } else {
                *(float2*)(outp + (size_t)tok0 * PC + f) = v0;
                *(float2*)(outp + (size_t)(tok0 + 8) * PC + f) = v1;
            }
        }
    }
}

// ---------------------------------------------------------------------------
// Tensor-core flash attention. Br=128, Bc=64, dk=64. Inputs are pre-split
// bf16 planes (q pre-scaled). cp.async double-buffered K/V. Writes y planes.
// ---------------------------------------------------------------------------
#define AROWB 144
#define AQH 0
#define AQL 18432
#define KVS 36864                  // start of KV stages
#define KVSTAGE 36864              // 4 planes x 64 x 144
#define ATT_SMEM (KVS + 2 * KVSTAGE)   // 110592

__device__ __forceinline__ void att_issue_kv(
    const __nv_bfloat16* const* kvb, uint32_t sb, int st, int kt, int tid)
{
    #pragma unroll
    for (int t = 0; t < 8; t++) {
        const int flat = t * 256 + tid;
        const int p = flat >> 9;
        const int ch = flat & 511;
        const int row = ch >> 3, q = ch & 7;
        cp16(sb + KVS + st * KVSTAGE + p * 9216 + row * AROWB + (q << 4),
             kvb[p] + ((size_t)kt * 64 + row) * PDK + q * 8);
    }
}

__global__ __launch_bounds__(256) void attn_tc_kernel()
{
    extern __shared__ __align__(16) char smem[];
    const uint32_t sb = smem_u32(smem);
    const int tid = threadIdx.x, wid = tid >> 5, lid = tid & 31;
    const int qt = blockIdx.x, hh = blockIdx.y, bidx = blockIdx.z;

    const size_t headoff = ((size_t)bidx * PH + hh) * PT * PDK;
    const __nv_bfloat16* qhb = g_qh + headoff + (size_t)qt * 128 * PDK;
    const __nv_bfloat16* qlb = g_ql + headoff + (size_t)qt * 128 * PDK;
    const __nv_bfloat16* kvb[4] = { g_kh + headoff, g_kl + headoff,
                                    g_vh + headoff, g_vl + headoff };

    // Q planes + KV stage 0 in group 0
    #pragma unroll
    for (int t = 0; t < 8; t++) {
        const int flat = t * 256 + tid;
        const int pl = flat >> 10;
        const int ch = flat & 1023;
        const int row = ch >> 3, q = ch & 7;
        cp16(sb + (pl ? AQL : AQH) + row * AROWB + (q << 4),
             (pl ? qlb : qhb) + (size_t)row * PDK + q * 8);
    }
    att_issue_kv(kvb, sb, 0, 0, tid);
    CP_COMMIT();

    float oc[8][4];
    #pragma unroll
    for (int nt = 0; nt < 8; nt++)
        #pragma unroll
        for (int e = 0; e < 4; e++) oc[nt][e] = 0.0f;
    float mrow[2] = {-CUDART_INF_F, -CUDART_INF_F};
    float lrow[2] = {0.0f, 0.0f};

    const int lr = lid & 15, lh = lid >> 4;

    for (int kt = 0; kt < PT / 64; kt++) {
        const int cur = kt & 1;
        if (kt + 1 < PT / 64) {
            att_issue_kv(kvb, sb, (kt + 1) & 1, kt + 1, tid);
            CP_COMMIT();
            CP_WAIT(1);
        } else {
            CP_WAIT(0);
        }
        __syncthreads();

        const uint32_t kh0 = sb + KVS + cur * KVSTAGE;
        const uint32_t kl0 = kh0 + 9216;
        const uint32_t vh0 = kh0 + 18432;
        const uint32_t vl0 = kh0 + 27648;

        // S = Q K^T
        float sc[8][4];
        #pragma unroll
        for (int nt = 0; nt < 8; nt++)
            #pragma unroll
            for (int e = 0; e < 4; e++) sc[nt][e] = 0.0f;
        #pragma unroll
        for (int k16 = 0; k16 < 4; k16++) {
            const uint32_t colb = (uint32_t)((k16 * 16 + lh * 8) * 2);
            uint32_t aqh[4], aql[4];
            const uint32_t qra = (uint32_t)((wid * 16 + lr) * AROWB) + colb;
            ldsm_x4(sb + AQH + qra, aqh[0], aqh[1], aqh[2], aqh[3]);
            ldsm_x4(sb + AQL + qra, aql[0], aql[1], aql[2], aql[3]);
            #pragma unroll
            for (int np = 0; np < 4; np++) {
                const uint32_t kra = (uint32_t)((np * 16 + lr) * AROWB) + colb;
                uint32_t h0, h1, h2, h3, l0, l1, l2, l3;
                ldsm_x4(kh0 + kra, h0, h1, h2, h3);
                ldsm_x4(kl0 + kra, l0, l1, l2, l3);
                mma16816(sc[2 * np], aqh, h0, h2);
                mma16816(sc[2 * np], aqh, l0, l2);
                mma16816(sc[2 * np], aql, h0, h2);
                mma16816(sc[2 * np + 1], aqh, h1, h3);
                mma16816(sc[2 * np + 1], aqh, l1, l3);
                mma16816(sc[2 * np + 1], aql, h1, h3);
            }
        }

        // Online softmax
        #pragma unroll
        for (int i = 0; i < 2; i++) {
            float mx = -CUDART_INF_F;
            #pragma unroll
            for (int nt = 0; nt < 8; nt++)
                mx = fmaxf(mx, fmaxf(sc[nt][2 * i], sc[nt][2 * i + 1]));
            mx = fmaxf(mx, __shfl_xor_sync(0xffffffffu, mx, 1));
            mx = fmaxf(mx, __shfl_xor_sync(0xffffffffu, mx, 2));
            const float mnew = fmaxf(mrow[i], mx);
            const float alpha = __expf(mrow[i] - mnew);
            mrow[i] = mnew;
            float rs = 0.0f;
            #pragma unroll
            for (int nt = 0; nt < 8; nt++) {
                const float p0 = __expf(sc[nt][2 * i] - mnew);
                const float p1 = __expf(sc[nt][2 * i + 1] - mnew);
                sc[nt][2 * i] = p0; sc[nt][2 * i + 1] = p1;
                rs += p0 + p1;
            }
            rs += __shfl_xor_sync(0xffffffffu, rs, 1);
            rs += __shfl_xor_sync(0xffffffffu, rs, 2);
            lrow[i] = lrow[i] * alpha + rs;
            #pragma unroll
            for (int nt = 0; nt < 8; nt++) {
                oc[nt][2 * i] *= alpha;
                oc[nt][2 * i + 1] *= alpha;
            }
        }

        // O += P V
        #pragma unroll
        for (int j16 = 0; j16 < 4; j16++) {
            uint32_t aph[4], apl[4];
            pack_split(sc[2 * j16][0], sc[2 * j16][1], aph[0], apl[0]);
            pack_split(sc[2 * j16][2], sc[2 * j16][3], aph[1], apl[1]);
            pack_split(sc[2 * j16 + 1][0], sc[2 * j16 + 1][1], aph[2], apl[2]);
            pack_split(sc[2 * j16 + 1][2], sc[2 * j16 + 1][3], aph[3], apl[3]);
            #pragma unroll
            for (int dp = 0; dp < 4; dp++) {
                const uint32_t vra = (uint32_t)((j16 * 16 + lr) * AROWB
                                                + (dp * 16 + lh * 8) * 2);
                uint32_t h0, h1, h2, h3, l0, l1, l2, l3;
                ldsm_x4t(vh0 + vra, h0, h1, h2, h3);
                ldsm_x4t(vl0 + vra, l0, l1, l2, l3);
                mma16816(oc[2 * dp], aph, h0, h1);
                mma16816(oc[2 * dp], aph, l0, l1);
                mma16816(oc[2 * dp], apl, h0, h1);
                mma16816(oc[2 * dp + 1], aph, h2, h3);
                mma16816(oc[2 * dp + 1], aph, l2, l3);
                mma16816(oc[2 * dp + 1], apl, h2, h3);
            }
        }
        __syncthreads();
    }

    // Epilogue: normalize, split, write y planes [B,T,C]
    const int r0 = lid >> 2, c0 = (lid & 3) << 1;
    #pragma unroll
    for (int i = 0; i < 2; i++) {
        const float inv = 1.0f / lrow[i];
        const int tok = qt * 128 + wid * 16 + r0 + i * 8;
        const size_t rowoff = ((size_t)bidx * PT + tok) * PC + hh * PDK;
        #pragma unroll
        for (int nt = 0; nt < 8; nt++) {
            uint32_t h, l;
            pack_split(oc[nt][2 * i] * inv, oc[nt][2 * i + 1] * inv, h, l);
            *(uint32_t*)(g_yh + rowoff + nt * 8 + c0) = h;
            *(uint32_t*)(g_yl + rowoff + nt * 8 + c0) = l;
        }
    }
}

// ---------------------------------------------------------------------------
extern "C" void kernel_launch(void* const* d_in, const int* in_sizes, int n_in,
                              void* d_out, int out_size)
{
    const float* x      = (const float*)d_in[0];
    const float* w_attn = (const float*)d_in[1];
    const float* b_attn = (const float*)d_in[2];
    const float* w_proj = (const float*)d_in[3];
    const float* b_proj = (const float*)d_in[4];
    float* out = (float*)d_out;

    cudaFuncSetAttribute(tc_gemm_kernel<0>,
                         cudaFuncAttributeMaxDynamicSharedMemorySize, GK_SMEM);
    cudaFuncSetAttribute(tc_gemm_kernel<1>,
                         cudaFuncAttributeMaxDynamicSharedMemorySize, GK_SMEM);
    cudaFuncSetAttribute(attn_tc_kernel,
                         cudaFuncAttributeMaxDynamicSharedMemorySize, ATT_SMEM);

    __nv_bfloat16 *xh, *xl, *yh, *yl, *wah, *wal, *wph, *wpl;
    cudaGetSymbolAddress((void**)&xh, g_xh);  cudaGetSymbolAddress((void**)&xl, g_xl);
    cudaGetSymbolAddress((void**)&yh, g_yh);  cudaGetSymbolAddress((void**)&yl, g_yl);
    cudaGetSymbolAddress((void**)&wah, g_wah); cudaGetSymbolAddress((void**)&wal, g_wal);
    cudaGetSymbolAddress((void**)&wph, g_wph); cudaGetSymbolAddress((void**)&wpl, g_wpl);

    conv_split_kernel<<<NTOK * PC / 1024, 256>>>(x, xh, xl);
    conv_split_kernel<<<M3 * PC / 1024, 256>>>(w_attn, wah, wal);
    conv_split_kernel<<<PC * PC / 1024, 256>>>(w_proj, wph, wpl);

    tc_gemm_kernel<0><<<dim3(M3 / 128, NTOK / 128), 256, GK_SMEM>>>(
        xh, xl, wah, wal, b_attn, nullptr);

    attn_tc_kernel<<<dim3(PT / 128, PH, PB), 256, ATT_SMEM>>>();

    tc_gemm_kernel<1><<<dim3(PC / 128, NTOK / 128), 256, GK_SMEM>>>(
        yh, yl, wph, wpl, b_proj, out);
}

// round 12
// speedup vs baseline: 5.3148x; 1.5332x over previous
#include <cuda_runtime.h>
#include <cuda_fp16.h>
#include <math_constants.h>
#include <cstdint>

// Problem constants
#define PB 4
#define PT 2048
#define PC 1024
#define PH 16
#define PDK 64
#define NTOK (PB * PT)      // 8192
#define M3 (3 * PC)         // 3072

// fp16 planes. Activations split hi/lo; weights/K/V single.
__device__ __half g_xh[NTOK * PC], g_xl[NTOK * PC];
__device__ __half g_yh[NTOK * PC], g_yl[NTOK * PC];
__device__ __half g_wa[M3 * PC];
__device__ __half g_wp[PC * PC];
__device__ __half g_qh[NTOK * PC], g_ql[NTOK * PC];   // q pre-scaled by 1/8
__device__ __half g_kk[NTOK * PC];
__device__ __half g_vv[NTOK * PC];

// ---------------------------------------------------------------------------
// Helpers
// ---------------------------------------------------------------------------
__device__ __forceinline__ uint32_t smem_u32(const void* p) {
    uint32_t a;
    asm("{ .reg .u64 t; cvta.to.shared.u64 t, %1; cvt.u32.u64 %0, t; }"
        : "=r"(a) : "l"(p));
    return a;
}
__device__ __forceinline__ void cp16(uint32_t dst, const void* src) {
    asm volatile("cp.async.cg.shared.global [%0], [%1], 16;"
                 :: "r"(dst), "l"(src));
}
#define CP_COMMIT() asm volatile("cp.async.commit_group;" ::: "memory")
#define CP_WAIT(n)  asm volatile("cp.async.wait_group %0;" :: "n"(n) : "memory")

__device__ __forceinline__ void ldsm_x4(uint32_t addr, uint32_t& r0, uint32_t& r1,
                                        uint32_t& r2, uint32_t& r3) {
    asm volatile("ldmatrix.sync.aligned.m8n8.x4.shared.b16 {%0,%1,%2,%3}, [%4];"
                 : "=r"(r0), "=r"(r1), "=r"(r2), "=r"(r3) : "r"(addr));
}
__device__ __forceinline__ void ldsm_x4t(uint32_t addr, uint32_t& r0, uint32_t& r1,
                                         uint32_t& r2, uint32_t& r3) {
    asm volatile("ldmatrix.sync.aligned.m8n8.x4.trans.shared.b16 {%0,%1,%2,%3}, [%4];"
                 : "=r"(r0), "=r"(r1), "=r"(r2), "=r"(r3) : "r"(addr));
}
__device__ __forceinline__ void mma16816(float* c, const uint32_t* a,
                                         uint32_t b0, uint32_t b1) {
    asm volatile(
        "mma.sync.aligned.m16n8k16.row.col.f32.f16.f16.f32 "
        "{%0,%1,%2,%3}, {%4,%5,%6,%7}, {%8,%9}, {%0,%1,%2,%3};"
        : "+f"(c[0]), "+f"(c[1]), "+f"(c[2]), "+f"(c[3])
        : "r"(a[0]), "r"(a[1]), "r"(a[2]), "r"(a[3]), "r"(b0), "r"(b1));
}
// fp32 pair -> fp16 hi + fp16 lo (lo = residual)
__device__ __forceinline__ void pack_split_h(float a, float b, uint32_t& hi, uint32_t& lo) {
    __half2 h = __floats2half2_rn(a, b);
    __half2 l = __floats2half2_rn(a - __low2float(h), b - __high2float(h));
    hi = *(const uint32_t*)&h;
    lo = *(const uint32_t*)&l;
}
__device__ __forceinline__ uint32_t pack_h2(float a, float b) {
    __half2 h = __floats2half2_rn(a, b);
    return *(const uint32_t*)&h;
}

// ---------------------------------------------------------------------------
// Conversions
// ---------------------------------------------------------------------------
__global__ __launch_bounds__(256) void conv_split_kernel(
    const float* __restrict__ src, __half* __restrict__ hi, __half* __restrict__ lo)
{
    const int i = (blockIdx.x * 256 + threadIdx.x) * 4;
    float4 v = *(const float4*)(src + i);
    uint32_t h0, l0, h1, l1;
    pack_split_h(v.x, v.y, h0, l0);
    pack_split_h(v.z, v.w, h1, l1);
    *(uint2*)(hi + i) = make_uint2(h0, h1);
    *(uint2*)(lo + i) = make_uint2(l0, l1);
}
__global__ __launch_bounds__(256) void conv_single_kernel(
    const float* __restrict__ src, __half* __restrict__ dst)
{
    const int i = (blockIdx.x * 256 + threadIdx.x) * 4;
    float4 v = *(const float4*)(src + i);
    *(uint2*)(dst + i) = make_uint2(pack_h2(v.x, v.y), pack_h2(v.z, v.w));
}

// ---------------------------------------------------------------------------
// Dense GEMM: D[m=token][n=feature] = (Ah+Al) * B^T + bias
// Block 128x128, K-chunk 64 per stage, 2 stages, 3 smem planes, 2 CTAs/SM.
// MODE 0: write q(hi/lo, x1/8), k(single), v(single). MODE 1: fp32 out.
// ---------------------------------------------------------------------------
#define GROWB 144                   // 64 halves = 128B + 16B pad
#define PLB (128 * GROWB)           // 18432 per plane
#define STAGEB (3 * PLB)            // Ah, Al, B
#define GK_SMEM (2 * STAGEB)        // 110592

__device__ __forceinline__ void gk_issue(
    const __half* const* srcs, uint32_t sbase, int st, int ks, int tid)
{
    #pragma unroll
    for (int t = 0; t < 12; t++) {
        const int flat = t * 256 + tid;
        const int p = flat >> 10;
        const int ch = flat & 1023;
        const int row = ch >> 3, q = ch & 7;
        cp16(sbase + st * STAGEB + p * PLB + row * GROWB + (q << 4),
             srcs[p] + (size_t)row * PC + ks * 64 + q * 8);
    }
}

template <int MODE>
__global__ __launch_bounds__(256, 2) void tc_gemm_kernel(
    const __half* __restrict__ Ah_g, const __half* __restrict__ Al_g,
    const __half* __restrict__ B_g,
    const float* __restrict__ bias, float* __restrict__ outp)
{
    extern __shared__ __align__(16) char smem[];
    const uint32_t sbase = smem_u32(smem);
    const int tid = threadIdx.x;
    const int wid = tid >> 5, lid = tid & 31;
    const int wm = wid >> 2, wn = wid & 3;
    const int fb = blockIdx.x * 128;
    const int mb = blockIdx.y * 128;

    const __half* srcs[3] = { Ah_g + (size_t)mb * PC, Al_g + (size_t)mb * PC,
                              B_g + (size_t)fb * PC };

    float c[4][4][4];
    #pragma unroll
    for (int i = 0; i < 4; i++)
        #pragma unroll
        for (int j = 0; j < 4; j++)
            #pragma unroll
            for (int e = 0; e < 4; e++) c[i][j][e] = 0.0f;

    gk_issue(srcs, sbase, 0, 0, tid);
    CP_COMMIT();

    const int lr = lid & 15;
    const int lh = lid >> 4;

    for (int ks = 0; ks < 16; ks++) {
        const int cur = ks & 1;
        if (ks + 1 < 16) {
            gk_issue(srcs, sbase, (ks + 1) & 1, ks + 1, tid);
            CP_COMMIT();
            CP_WAIT(1);
        } else {
            CP_WAIT(0);
        }
        __syncthreads();

        const uint32_t stb = sbase + cur * STAGEB;
        #pragma unroll
        for (int k16 = 0; k16 < 4; k16++) {
            const uint32_t colb = (uint32_t)(k16 * 32 + lh * 16);
            uint32_t ah[4][4], al[4][4];
            #pragma unroll
            for (int mt = 0; mt < 4; mt++) {
                const uint32_t ra = (wm * 64 + mt * 16 + lr) * GROWB + colb;
                ldsm_x4(stb + 0 * PLB + ra, ah[mt][0], ah[mt][1], ah[mt][2], ah[mt][3]);
                ldsm_x4(stb + 1 * PLB + ra, al[mt][0], al[mt][1], al[mt][2], al[mt][3]);
            }
            uint32_t bf[4][2];
            #pragma unroll
            for (int np = 0; np < 2; np++) {
                const uint32_t rb = (wn * 32 + np * 16 + lr) * GROWB + colb;
                uint32_t r0, r1, r2, r3;
                ldsm_x4(stb + 2 * PLB + rb, r0, r1, r2, r3);
                bf[np * 2][0] = r0; bf[np * 2][1] = r2;
                bf[np * 2 + 1][0] = r1; bf[np * 2 + 1][1] = r3;
            }
            #pragma unroll
            for (int mt = 0; mt < 4; mt++)
                #pragma unroll
                for (int nt = 0; nt < 4; nt++) {
                    mma16816(c[mt][nt], ah[mt], bf[nt][0], bf[nt][1]);
                    mma16816(c[mt][nt], al[mt], bf[nt][0], bf[nt][1]);
                }
        }
        __syncthreads();
    }

    const int r0 = lid >> 2;
    const int c0 = (lid & 3) << 1;
    #pragma unroll
    for (int mt = 0; mt < 4; mt++) {
        #pragma unroll
        for (int nt = 0; nt < 4; nt++) {
            const int f = fb + wn * 32 + nt * 8 + c0;
            const float2 b2 = *(const float2*)(bias + f);
            const int tok0 = mb + wm * 64 + mt * 16 + r0;
            float2 v0 = make_float2(c[mt][nt][0] + b2.x, c[mt][nt][1] + b2.y);
            float2 v1 = make_float2(c[mt][nt][2] + b2.x, c[mt][nt][3] + b2.y);
            if (MODE == 0) {
                const int sec = f >> 10;
                const int cc = f & (PC - 1);
                const int hh = cc >> 6, d = cc & 63;
                const int b = tok0 >> 11;
                const int tk = tok0 & (PT - 1);
                const size_t base = (((size_t)b * PH + hh) * PT + tk) * PDK + d;
                if (sec == 0) {
                    uint32_t h, l;
                    pack_split_h(v0.x * 0.125f, v0.y * 0.125f, h, l);
                    *(uint32_t*)(g_qh + base) = h;
                    *(uint32_t*)(g_ql + base) = l;
                    pack_split_h(v1.x * 0.125f, v1.y * 0.125f, h, l);
                    *(uint32_t*)(g_qh + base + 8 * PDK) = h;
                    *(uint32_t*)(g_ql + base + 8 * PDK) = l;
                } else {
                    __half* dst = (sec == 1) ? g_kk : g_vv;
                    *(uint32_t*)(dst + base) = pack_h2(v0.x, v0.y);
                    *(uint32_t*)(dst + base + 8 * PDK) = pack_h2(v1.x, v1.y);
                }
            } else {
                *(float2*)(outp + (size_t)tok0 * PC + f) = v0;
                *(float2*)(outp + (size_t)(tok0 + 8) * PC + f) = v1;
            }
        }
    }
}

// ---------------------------------------------------------------------------
// Flash attention. Br=128, Bc=64, dk=64. Q hi/lo fp16 (pre-scaled); K,V single.
// S = Qh K^T + Ql K^T; O += Ph V + Pl V. Writes y hi/lo planes.
// ---------------------------------------------------------------------------
#define AROWB 144
#define AQH 0
#define AQL 18432
#define KVS 36864
#define KVSTAGE 18432              // K(9216) + V(9216)
#define ATT_SMEM (KVS + 2 * KVSTAGE)   // 73728

__device__ __forceinline__ void att_issue_kv(
    const __half* const* kvb, uint32_t sb, int st, int kt, int tid)
{
    #pragma unroll
    for (int t = 0; t < 4; t++) {
        const int flat = t * 256 + tid;
        const int p = flat >> 9;
        const int ch = flat & 511;
        const int row = ch >> 3, q = ch & 7;
        cp16(sb + KVS + st * KVSTAGE + p * 9216 + row * AROWB + (q << 4),
             kvb[p] + ((size_t)kt * 64 + row) * PDK + q * 8);
    }
}

__global__ __launch_bounds__(256) void attn_tc_kernel()
{
    extern __shared__ __align__(16) char smem[];
    const uint32_t sb = smem_u32(smem);
    const int tid = threadIdx.x, wid = tid >> 5, lid = tid & 31;
    const int qt = blockIdx.x, hh = blockIdx.y, bidx = blockIdx.z;

    const size_t headoff = ((size_t)bidx * PH + hh) * PT * PDK;
    const __half* qhb = g_qh + headoff + (size_t)qt * 128 * PDK;
    const __half* qlb = g_ql + headoff + (size_t)qt * 128 * PDK;
    const __half* kvb[2] = { g_kk + headoff, g_vv + headoff };

    #pragma unroll
    for (int t = 0; t < 8; t++) {
        const int flat = t * 256 + tid;
        const int pl = flat >> 10;
        const int ch = flat & 1023;
        const int row = ch >> 3, q = ch & 7;
        cp16(sb + (pl ? AQL : AQH) + row * AROWB + (q << 4),
             (pl ? qlb : qhb) + (size_t)row * PDK + q * 8);
    }
    att_issue_kv(kvb, sb, 0, 0, tid);
    CP_COMMIT();

    float oc[8][4];
    #pragma unroll
    for (int nt = 0; nt < 8; nt++)
        #pragma unroll
        for (int e = 0; e < 4; e++) oc[nt][e] = 0.0f;
    float mrow[2] = {-CUDART_INF_F, -CUDART_INF_F};
    float lrow[2] = {0.0f, 0.0f};

    const int lr = lid & 15, lh = lid >> 4;

    for (int kt = 0; kt < PT / 64; kt++) {
        const int cur = kt & 1;
        if (kt + 1 < PT / 64) {
            att_issue_kv(kvb, sb, (kt + 1) & 1, kt + 1, tid);
            CP_COMMIT();
            CP_WAIT(1);
        } else {
            CP_WAIT(0);
        }
        __syncthreads();

        const uint32_t k0 = sb + KVS + cur * KVSTAGE;
        const uint32_t v0 = k0 + 9216;

        // S = Q K^T
        float sc[8][4];
        #pragma unroll
        for (int nt = 0; nt < 8; nt++)
            #pragma unroll
            for (int e = 0; e < 4; e++) sc[nt][e] = 0.0f;
        #pragma unroll
        for (int k16 = 0; k16 < 4; k16++) {
            const uint32_t colb = (uint32_t)((k16 * 16 + lh * 8) * 2);
            uint32_t aqh[4], aql[4];
            const uint32_t qra = (uint32_t)((wid * 16 + lr) * AROWB) + colb;
            ldsm_x4(sb + AQH + qra, aqh[0], aqh[1], aqh[2], aqh[3]);
            ldsm_x4(sb + AQL + qra, aql[0], aql[1], aql[2], aql[3]);
            #pragma unroll
            for (int np = 0; np < 4; np++) {
                const uint32_t kra = (uint32_t)((np * 16 + lr) * AROWB) + colb;
                uint32_t h0, h1, h2, h3;
                ldsm_x4(k0 + kra, h0, h1, h2, h3);
                mma16816(sc[2 * np], aqh, h0, h2);
                mma16816(sc[2 * np], aql, h0, h2);
                mma16816(sc[2 * np + 1], aqh, h1, h3);
                mma16816(sc[2 * np + 1], aql, h1, h3);
            }
        }

        // Online softmax
        #pragma unroll
        for (int i = 0; i < 2; i++) {
            float mx = -CUDART_INF_F;
            #pragma unroll
            for (int nt = 0; nt < 8; nt++)
                mx = fmaxf(mx, fmaxf(sc[nt][2 * i], sc[nt][2 * i + 1]));
            mx = fmaxf(mx, __shfl_xor_sync(0xffffffffu, mx, 1));
            mx = fmaxf(mx, __shfl_xor_sync(0xffffffffu, mx, 2));
            const float mnew = fmaxf(mrow[i], mx);
            const float alpha = __expf(mrow[i] - mnew);
            mrow[i] = mnew;
            float rs = 0.0f;
            #pragma unroll
            for (int nt = 0; nt < 8; nt++) {
                const float p0 = __expf(sc[nt][2 * i] - mnew);
                const float p1 = __expf(sc[nt][2 * i + 1] - mnew);
                sc[nt][2 * i] = p0; sc[nt][2 * i + 1] = p1;
                rs += p0 + p1;
            }
            rs += __shfl_xor_sync(0xffffffffu, rs, 1);
            rs += __shfl_xor_sync(0xffffffffu, rs, 2);
            lrow[i] = lrow[i] * alpha + rs;
            #pragma unroll
            for (int nt = 0; nt < 8; nt++) {
                oc[nt][2 * i] *= alpha;
                oc[nt][2 * i + 1] *= alpha;
            }
        }

        // O += P V
        #pragma unroll
        for (int j16 = 0; j16 < 4; j16++) {
            uint32_t aph[4], apl[4];
            pack_split_h(sc[2 * j16][0], sc[2 * j16][1], aph[0], apl[0]);
            pack_split_h(sc[2 * j16][2], sc[2 * j16][3], aph[1], apl[1]);
            pack_split_h(sc[2 * j16 + 1][0], sc[2 * j16 + 1][1], aph[2], apl[2]);
            pack_split_h(sc[2 * j16 + 1][2], sc[2 * j16 + 1][3], aph[3], apl[3]);
            #pragma unroll
            for (int dp = 0; dp < 4; dp++) {
                const uint32_t vra = (uint32_t)((j16 * 16 + lr) * AROWB
                                                + (dp * 16 + lh * 8) * 2);
                uint32_t h0, h1, h2, h3;
                ldsm_x4t(v0 + vra, h0, h1, h2, h3);
                mma16816(oc[2 * dp], aph, h0, h1);
                mma16816(oc[2 * dp], apl, h0, h1);
                mma16816(oc[2 * dp + 1], aph, h2, h3);
                mma16816(oc[2 * dp + 1], apl, h2, h3);
            }
        }
        __syncthreads();
    }

    // Epilogue: normalize, write y hi/lo planes [B,T,C]
    const int r0 = lid >> 2, c0 = (lid & 3) << 1;
    #pragma unroll
    for (int i = 0; i < 2; i++) {
        const float inv = 1.0f / lrow[i];
        const int tok = qt * 128 + wid * 16 + r0 + i * 8;
        const size_t rowoff = ((size_t)bidx * PT + tok) * PC + hh * PDK;
        #pragma unroll
        for (int nt = 0; nt < 8; nt++) {
            uint32_t h, l;
            pack_split_h(oc[nt][2 * i] * inv, oc[nt][2 * i + 1] * inv, h, l);
            *(uint32_t*)(g_yh + rowoff + nt * 8 + c0) = h;
            *(uint32_t*)(g_yl + rowoff + nt * 8 + c0) = l;
        }
    }
}

// ---------------------------------------------------------------------------
extern "C" void kernel_launch(void* const* d_in, const int* in_sizes, int n_in,
                              void* d_out, int out_size)
{
    const float* x      = (const float*)d_in[0];
    const float* w_attn = (const float*)d_in[1];
    const float* b_attn = (const float*)d_in[2];
    const float* w_proj = (const float*)d_in[3];
    const float* b_proj = (const float*)d_in[4];
    float* out = (float*)d_out;

    cudaFuncSetAttribute(tc_gemm_kernel<0>,
                         cudaFuncAttributeMaxDynamicSharedMemorySize, GK_SMEM);
    cudaFuncSetAttribute(tc_gemm_kernel<1>,
                         cudaFuncAttributeMaxDynamicSharedMemorySize, GK_SMEM);
    cudaFuncSetAttribute(attn_tc_kernel,
                         cudaFuncAttributeMaxDynamicSharedMemorySize, ATT_SMEM);

    __half *xh, *xl, *yh, *yl, *wa, *wp;
    cudaGetSymbolAddress((void**)&xh, g_xh);  cudaGetSymbolAddress((void**)&xl, g_xl);
    cudaGetSymbolAddress((void**)&yh, g_yh);  cudaGetSymbolAddress((void**)&yl, g_yl);
    cudaGetSymbolAddress((void**)&wa, g_wa);  cudaGetSymbolAddress((void**)&wp, g_wp);

    conv_split_kernel<<<NTOK * PC / 1024, 256>>>(x, xh, xl);
    conv_single_kernel<<<M3 * PC / 1024, 256>>>(w_attn, wa);
    conv_single_kernel<<<PC * PC / 1024, 256>>>(w_proj, wp);

    tc_gemm_kernel<0><<<dim3(M3 / 128, NTOK / 128), 256, GK_SMEM>>>(
        xh, xl, wa, b_attn, nullptr);

    attn_tc_kernel<<<dim3(PT / 128, PH, PB), 256, ATT_SMEM>>>();

    tc_gemm_kernel<1><<<dim3(PC / 128, NTOK / 128), 256, GK_SMEM>>>(
        yh, yl, wp, b_proj, out);
}